// round 4
// baseline (speedup 1.0000x reference)
#include <cuda_runtime.h>

// ---------------------------------------------------------------------------
// Pin2PinAttraction: out = sum_j w[j] * ((x[a_j]-x[b_j])^2 + (y[a_j]-y[b_j])^2)
// Single fused kernel:
//   phase 1: pack (x,y) -> float2 scratch (+ block 0 detects pairs dtype)
//   grid barrier (co-residency guaranteed via occupancy query)
//   phase 2: gather + reduce; last block writes d_out and resets state.
// ---------------------------------------------------------------------------

#define MAX_PINS 2000000
#define NTHREADS 256

__device__ float2       g_xy[MAX_PINS];   // 16 MB static scratch — legal
__device__ double       g_sum;            // zero-init; reset by last block
__device__ unsigned int g_bar;            // pack->gather grid barrier
__device__ unsigned int g_count;          // completion counter
__device__ int          g_is64;

__global__ void __launch_bounds__(NTHREADS)
fused_kernel(const float* __restrict__ pin_pos, int num_pins,
             const void* __restrict__ pairs_raw,
             const float* __restrict__ weights, int num_pairs,
             float* __restrict__ out) {
    const int tid    = blockIdx.x * blockDim.x + threadIdx.x;
    const int stride = gridDim.x * blockDim.x;

    // ---------- Phase 1: dtype detection (block 0) ----------
    // int64 pairs (>=0, < 2^31, little-endian) have zero high words at word
    // indices 4i+1, 4i+3. int32 pairs put b-indices there — over 8K samples
    // essentially never all zero.
    if (blockIdx.x == 0) {
        __shared__ int s_nz[NTHREADS];
        const int* __restrict__ p32 = (const int*)pairs_raw;
        int t = threadIdx.x;
        int nz = 0;
        for (int i = t; i < 8192; i += NTHREADS)
            nz |= p32[4 * i + 1] | p32[4 * i + 3];
        s_nz[t] = nz;
        __syncthreads();
        for (int s = NTHREADS / 2; s > 0; s >>= 1) {
            if (t < s) s_nz[t] |= s_nz[t + s];
            __syncthreads();
        }
        if (t == 0) g_is64 = (s_nz[0] == 0) ? 1 : 0;
    }

    // ---------- Phase 1: pack x,y into float2 (all blocks) ----------
    {
        const float4* __restrict__ xs4 = (const float4*)pin_pos;
        const float4* __restrict__ ys4 = (const float4*)(pin_pos + num_pins);
        int n4 = num_pins >> 2;
        for (int i = tid; i < n4; i += stride) {
            float4 x = __ldg(&xs4[i]);
            float4 y = __ldg(&ys4[i]);
            int b = i << 2;
            g_xy[b + 0] = make_float2(x.x, y.x);
            g_xy[b + 1] = make_float2(x.y, y.y);
            g_xy[b + 2] = make_float2(x.z, y.z);
            g_xy[b + 3] = make_float2(x.w, y.w);
        }
        for (int i = (n4 << 2) + tid; i < num_pins; i += stride)
            g_xy[i] = make_float2(__ldg(&pin_pos[i]),
                                  __ldg(&pin_pos[num_pins + i]));
    }

    // ---------- Grid barrier (all blocks co-resident by construction) ------
    __syncthreads();
    if (threadIdx.x == 0) {
        __threadfence();                      // publish g_xy / g_is64
        atomicAdd(&g_bar, 1u);
        while (atomicAdd(&g_bar, 0u) < gridDim.x)
            __nanosleep(64);
    }
    __syncthreads();
    __threadfence();                          // acquire g_xy / g_is64

    // ---------- Phase 2: gather + reduce ----------
    const int is64 = g_is64;
    float acc0 = 0.0f, acc1 = 0.0f;

    if (is64) {
        const int4* __restrict__ p4 = (const int4*)pairs_raw;
        int j = tid;
        for (; j + stride < num_pairs; j += 2 * stride) {
            int4  pA = __ldcs(&p4[j]);
            int4  pB = __ldcs(&p4[j + stride]);
            float wA = __ldcs(&weights[j]);
            float wB = __ldcs(&weights[j + stride]);
            float2 a0 = __ldg(&g_xy[pA.x]);
            float2 b0 = __ldg(&g_xy[pA.z]);
            float2 a1 = __ldg(&g_xy[pB.x]);
            float2 b1 = __ldg(&g_xy[pB.z]);
            float dx0 = a0.x - b0.x, dy0 = a0.y - b0.y;
            float dx1 = a1.x - b1.x, dy1 = a1.y - b1.y;
            acc0 = fmaf(wA, fmaf(dx0, dx0, dy0 * dy0), acc0);
            acc1 = fmaf(wB, fmaf(dx1, dx1, dy1 * dy1), acc1);
        }
        if (j < num_pairs) {
            int4  p = __ldcs(&p4[j]);
            float w = __ldcs(&weights[j]);
            float2 a = __ldg(&g_xy[p.x]);
            float2 b = __ldg(&g_xy[p.z]);
            float dx = a.x - b.x, dy = a.y - b.y;
            acc0 = fmaf(w, fmaf(dx, dx, dy * dy), acc0);
        }
    } else {
        const int2* __restrict__ p2 = (const int2*)pairs_raw;
        int j = tid;
        for (; j + stride < num_pairs; j += 2 * stride) {
            int2  pA = __ldcs(&p2[j]);
            int2  pB = __ldcs(&p2[j + stride]);
            float wA = __ldcs(&weights[j]);
            float wB = __ldcs(&weights[j + stride]);
            float2 a0 = __ldg(&g_xy[pA.x]);
            float2 b0 = __ldg(&g_xy[pA.y]);
            float2 a1 = __ldg(&g_xy[pB.x]);
            float2 b1 = __ldg(&g_xy[pB.y]);
            float dx0 = a0.x - b0.x, dy0 = a0.y - b0.y;
            float dx1 = a1.x - b1.x, dy1 = a1.y - b1.y;
            acc0 = fmaf(wA, fmaf(dx0, dx0, dy0 * dy0), acc0);
            acc1 = fmaf(wB, fmaf(dx1, dx1, dy1 * dy1), acc1);
        }
        if (j < num_pairs) {
            int2  p = __ldcs(&p2[j]);
            float w = __ldcs(&weights[j]);
            float2 a = __ldg(&g_xy[p.x]);
            float2 b = __ldg(&g_xy[p.y]);
            float dx = a.x - b.x, dy = a.y - b.y;
            acc0 = fmaf(w, fmaf(dx, dx, dy * dy), acc0);
        }
    }

    float acc = acc0 + acc1;

    // warp reduce
    #pragma unroll
    for (int off = 16; off > 0; off >>= 1)
        acc += __shfl_xor_sync(0xFFFFFFFFu, acc, off);

    __shared__ float s_warp[NTHREADS / 32];
    int lane = threadIdx.x & 31;
    int wid  = threadIdx.x >> 5;
    if (lane == 0) s_warp[wid] = acc;
    __syncthreads();

    if (threadIdx.x == 0) {
        double blk = 0.0;
        #pragma unroll
        for (int w = 0; w < NTHREADS / 32; w++) blk += (double)s_warp[w];
        atomicAdd(&g_sum, blk);
        __threadfence();
        unsigned int done = atomicAdd(&g_count, 1u);
        if (done == gridDim.x - 1) {
            __threadfence();                  // all g_sum contributions visible
            out[0] = (float)g_sum;
            // reset state for the next graph replay (deterministic)
            g_sum   = 0.0;
            g_count = 0u;
            g_bar   = 0u;
            __threadfence();
        }
    }
}

extern "C" void kernel_launch(void* const* d_in, const int* in_sizes, int n_in,
                              void* d_out, int out_size) {
    const float* pin_pos = (const float*)d_in[0];
    const float* weights = (const float*)d_in[1];
    const void*  pairs   = d_in[2];
    // d_in[3] = pin_mask (unused by reference)

    int num_pins  = in_sizes[0] / 2;
    int num_pairs = in_sizes[1];

    // Grid must be fully co-resident for the software grid barrier.
    int num_sms = 0, blocks_per_sm = 0;
    cudaDeviceGetAttribute(&num_sms, cudaDevAttrMultiProcessorCount, 0);
    cudaOccupancyMaxActiveBlocksPerMultiprocessor(&blocks_per_sm, fused_kernel,
                                                  NTHREADS, 0);
    if (num_sms <= 0)      num_sms = 148;
    if (blocks_per_sm <= 0) blocks_per_sm = 4;
    int grid = num_sms * blocks_per_sm;

    fused_kernel<<<grid, NTHREADS>>>(pin_pos, num_pins, pairs, weights,
                                     num_pairs, (float*)d_out);
}

// round 5
// speedup vs baseline: 1.0237x; 1.0237x over previous
#include <cuda_runtime.h>

// ---------------------------------------------------------------------------
// Pin2PinAttraction: out = sum_j w[j] * ((x[a_j]-x[b_j])^2 + (y[a_j]-y[b_j])^2)
//   K1: pack (x,y)->float2 scratch; block 0 detects pairs dtype + resets state.
//   K2: gather+reduce with WORK-STEALING chunks; last block writes d_out.
// ---------------------------------------------------------------------------

#define MAX_PINS   2000000
#define NBLOCKS    1184          // 8 CTAs per SM on 148 SMs
#define NTHREADS   256
#define CHUNK      2048          // pairs per stolen chunk (8 per thread)

__device__ float2       g_xy[MAX_PINS];   // 16 MB static scratch — legal
__device__ double       g_sum;
__device__ unsigned int g_count;
__device__ unsigned int g_chunk;          // work-stealing cursor
__device__ int          g_is64;

// --- Kernel 1: pack x,y into float2; block 0 detects dtype + resets ---------
__global__ void pack_kernel(const float* __restrict__ pin_pos, int num_pins,
                            const int* __restrict__ pairs32) {
    // int64 pairs (>=0, < 2^31, LE) have zero high words at word indices
    // 4i+1, 4i+3. int32 pairs put b-indices there — over 8K samples
    // essentially never all zero.
    if (blockIdx.x == 0) {
        __shared__ int s_nz[NTHREADS];
        int t = threadIdx.x;
        int nz = 0;
        for (int i = t; i < 8192; i += NTHREADS)
            nz |= pairs32[4 * i + 1] | pairs32[4 * i + 3];
        s_nz[t] = nz;
        __syncthreads();
        for (int s = NTHREADS / 2; s > 0; s >>= 1) {
            if (t < s) s_nz[t] |= s_nz[t + s];
            __syncthreads();
        }
        if (t == 0) {
            g_is64  = (s_nz[0] == 0) ? 1 : 0;
            g_sum   = 0.0;
            g_count = 0u;
            g_chunk = 0u;
        }
    }

    const float4* __restrict__ xs4 = (const float4*)pin_pos;
    const float4* __restrict__ ys4 = (const float4*)(pin_pos + num_pins);
    int n4 = num_pins >> 2;
    int stride = gridDim.x * blockDim.x;
    for (int i = blockIdx.x * blockDim.x + threadIdx.x; i < n4; i += stride) {
        float4 x = __ldg(&xs4[i]);
        float4 y = __ldg(&ys4[i]);
        int b = i << 2;
        g_xy[b + 0] = make_float2(x.x, y.x);
        g_xy[b + 1] = make_float2(x.y, y.y);
        g_xy[b + 2] = make_float2(x.z, y.z);
        g_xy[b + 3] = make_float2(x.w, y.w);
    }
    for (int i = (n4 << 2) + blockIdx.x * blockDim.x + threadIdx.x;
         i < num_pins; i += stride)
        g_xy[i] = make_float2(__ldg(&pin_pos[i]), __ldg(&pin_pos[num_pins + i]));
}

// --- Kernel 2: work-stealing gather + reduce + last-block writeout ----------
__global__ void __launch_bounds__(NTHREADS)
attraction_kernel(const void* __restrict__ pairs_raw,
                  const float* __restrict__ weights,
                  int num_pairs,
                  float* __restrict__ out) {
    const int is64 = g_is64;
    const unsigned int num_chunks =
        ((unsigned)num_pairs + CHUNK - 1) / CHUNK;

    __shared__ unsigned int s_chunk;
    float acc0 = 0.0f, acc1 = 0.0f;

    const int4* __restrict__ p4 = (const int4*)pairs_raw;
    const int2* __restrict__ p2 = (const int2*)pairs_raw;

    for (;;) {
        if (threadIdx.x == 0) s_chunk = atomicAdd(&g_chunk, 1u);
        __syncthreads();
        unsigned int c = s_chunk;
        if (c >= num_chunks) break;
        int base = (int)(c * CHUNK);

        if (base + CHUNK <= num_pairs) {
            // full chunk: 8 pairs per thread, 2x unrolled, coalesced stride 256
            int j = base + threadIdx.x;
            if (is64) {
                #pragma unroll
                for (int u = 0; u < CHUNK / (2 * NTHREADS); u++) {
                    int4  pA = __ldcs(&p4[j]);
                    int4  pB = __ldcs(&p4[j + NTHREADS]);
                    float wA = __ldcs(&weights[j]);
                    float wB = __ldcs(&weights[j + NTHREADS]);
                    float2 a0 = __ldg(&g_xy[pA.x]);
                    float2 b0 = __ldg(&g_xy[pA.z]);
                    float2 a1 = __ldg(&g_xy[pB.x]);
                    float2 b1 = __ldg(&g_xy[pB.z]);
                    float dx0 = a0.x - b0.x, dy0 = a0.y - b0.y;
                    float dx1 = a1.x - b1.x, dy1 = a1.y - b1.y;
                    acc0 = fmaf(wA, fmaf(dx0, dx0, dy0 * dy0), acc0);
                    acc1 = fmaf(wB, fmaf(dx1, dx1, dy1 * dy1), acc1);
                    j += 2 * NTHREADS;
                }
            } else {
                #pragma unroll
                for (int u = 0; u < CHUNK / (2 * NTHREADS); u++) {
                    int2  pA = __ldcs(&p2[j]);
                    int2  pB = __ldcs(&p2[j + NTHREADS]);
                    float wA = __ldcs(&weights[j]);
                    float wB = __ldcs(&weights[j + NTHREADS]);
                    float2 a0 = __ldg(&g_xy[pA.x]);
                    float2 b0 = __ldg(&g_xy[pA.y]);
                    float2 a1 = __ldg(&g_xy[pB.x]);
                    float2 b1 = __ldg(&g_xy[pB.y]);
                    float dx0 = a0.x - b0.x, dy0 = a0.y - b0.y;
                    float dx1 = a1.x - b1.x, dy1 = a1.y - b1.y;
                    acc0 = fmaf(wA, fmaf(dx0, dx0, dy0 * dy0), acc0);
                    acc1 = fmaf(wB, fmaf(dx1, dx1, dy1 * dy1), acc1);
                    j += 2 * NTHREADS;
                }
            }
        } else {
            // tail chunk (guarded)
            for (int j = base + threadIdx.x; j < num_pairs; j += NTHREADS) {
                float w = __ldcs(&weights[j]);
                float2 a, b;
                if (is64) {
                    int4 p = __ldcs(&p4[j]);
                    a = __ldg(&g_xy[p.x]);
                    b = __ldg(&g_xy[p.z]);
                } else {
                    int2 p = __ldcs(&p2[j]);
                    a = __ldg(&g_xy[p.x]);
                    b = __ldg(&g_xy[p.y]);
                }
                float dx = a.x - b.x, dy = a.y - b.y;
                acc0 = fmaf(w, fmaf(dx, dx, dy * dy), acc0);
            }
        }
    }

    float acc = acc0 + acc1;

    // warp reduce
    #pragma unroll
    for (int off = 16; off > 0; off >>= 1)
        acc += __shfl_xor_sync(0xFFFFFFFFu, acc, off);

    __shared__ float s_warp[NTHREADS / 32];
    int lane = threadIdx.x & 31;
    int wid  = threadIdx.x >> 5;
    if (lane == 0) s_warp[wid] = acc;
    __syncthreads();

    if (threadIdx.x == 0) {
        double blk = 0.0;
        #pragma unroll
        for (int w = 0; w < NTHREADS / 32; w++) blk += (double)s_warp[w];
        atomicAdd(&g_sum, blk);
        __threadfence();
        unsigned int done = atomicAdd(&g_count, 1u);
        if (done == gridDim.x - 1) {
            __threadfence();
            out[0] = (float)g_sum;
        }
    }
}

extern "C" void kernel_launch(void* const* d_in, const int* in_sizes, int n_in,
                              void* d_out, int out_size) {
    const float* pin_pos = (const float*)d_in[0];
    const float* weights = (const float*)d_in[1];
    const void*  pairs   = d_in[2];
    // d_in[3] = pin_mask (unused by reference)

    int num_pins  = in_sizes[0] / 2;
    int num_pairs = in_sizes[1];

    int pack_blocks = ((num_pins >> 2) + NTHREADS - 1) / NTHREADS;
    if (pack_blocks > 2048) pack_blocks = 2048;
    if (pack_blocks < 1)    pack_blocks = 1;
    pack_kernel<<<pack_blocks, NTHREADS>>>(pin_pos, num_pins, (const int*)pairs);

    attraction_kernel<<<NBLOCKS, NTHREADS>>>(pairs, weights, num_pairs,
                                             (float*)d_out);
}